// round 8
// baseline (speedup 1.0000x reference)
#include <cuda_runtime.h>
#include <math.h>

// VQ on GB300: int8 DP4A screening GEMM (int32-exact dots) + certified window
// + exact fp32 rescore => bit-exact reference argmins.
#define C_DIM 128
#define HW 4096
#define BN 64
#define N_TILES 4096
#define NTH 256
#define GRID 148
#define NQ 33554432
#define N_TOT 262144
#define CAP 8

// smem byte offsets
#define E_OFF    0          // emb fp32 [k][132] (135168)
#define ZF_OFF   135168     // z fp32 [c][68] (34816)
#define ZQ_OFF   169984     // zq int32 [c4=32][64] (8192)
#define EQ_OFF   178176     // eq int32 [c4=32][256] (32768)
#define SE_OFF   210944     // se[256]
#define SE1_OFF  211968     // Se1[256]
#define AN_OFF   212992     // An[64]
#define SZ1_OFF  213248     // Sz1[64]
#define WIN_OFF  213504     // win[64]
#define ALP_OFF  213760     // -2*alpha[64]
#define RED_OFF  214016     // partials 3x[4][64] (3072)
#define CNT_OFF  217088     // cnt[64]
#define CAND_OFF 217344     // cand[64][CAP] (2048)
#define IDX_OFF  219392     // idx_s[64]
#define QIN_OFF  219648     // qinv[64]
#define MISC_OFF 219904     // +0 see, +4 inv_see, +8 Se1max, +16 wsum[8], +48 scratch
#define SMEM_BYTES 219968

__device__ double d_loss_arr[GRID];

__device__ __forceinline__ unsigned fkey(float d){
    unsigned u=__float_as_uint(d); return ((int)u<0)?~u:(u|0x80000000u);
}

__global__ void __launch_bounds__(NTH,1)
vq_main(const float* __restrict__ z, const float* __restrict__ emb,
        float* __restrict__ out_q, float* __restrict__ out_idx){
    extern __shared__ char smx[];
    float* E   =(float*)(smx+E_OFF);
    float* zf  =(float*)(smx+ZF_OFF);
    int*   zq  =(int*)(smx+ZQ_OFF);
    int*   eq  =(int*)(smx+EQ_OFF);
    float* se  =(float*)(smx+SE_OFF);
    float* Se1 =(float*)(smx+SE1_OFF);
    float* An  =(float*)(smx+AN_OFF);
    float* Sz1 =(float*)(smx+SZ1_OFF);
    float* win =(float*)(smx+WIN_OFF);
    float* alp =(float*)(smx+ALP_OFF);
    float* RA  =(float*)(smx+RED_OFF);          // [4][64] A partials
    float* RS  =(float*)(smx+RED_OFF+1024);     // [4][64] abs-sum
    float* RM  =(float*)(smx+RED_OFF+2048);     // [4][64] max
    int*   cnt =(int*)(smx+CNT_OFF);
    int*   cand=(int*)(smx+CAND_OFF);
    int*   idx_s=(int*)(smx+IDX_OFF);
    float* qin =(float*)(smx+QIN_OFF);
    float* misc=(float*)(smx+MISC_OFF);
    float* wsum=misc+4;

    const int tid=threadIdx.x, lane=tid&31, w=tid>>5;

    // ================= prologue (emb) =================
    float mxe=0.f;
    {
        int k=tid;
        const float4* er=(const float4*)(emb+(size_t)k*C_DIM);
        float s=0.f, s1=0.f;
        #pragma unroll 8
        for(int i=0;i<32;++i){
            float4 v=er[i];
            *(float4*)(E+k*132+i*4)=v;
            s=__fmaf_rn(v.x,v.x,s); s=__fmaf_rn(v.y,v.y,s);
            s=__fmaf_rn(v.z,v.z,s); s=__fmaf_rn(v.w,v.w,s);
            s1+=fabsf(v.x)+fabsf(v.y)+fabsf(v.z)+fabsf(v.w);
            mxe=fmaxf(mxe,fmaxf(fmaxf(fabsf(v.x),fabsf(v.y)),fmaxf(fabsf(v.z),fabsf(v.w))));
        }
        se[k]=s; Se1[k]=s1;
    }
    __syncthreads();
    // block-reduce max|e| and max Se1
    {
        #pragma unroll
        for(int o=16;o>0;o>>=1) mxe=fmaxf(mxe,__shfl_xor_sync(0xFFFFFFFFu,mxe,o));
        if(lane==0) wsum[w]=mxe;
        __syncthreads();
        if(tid==0){
            float m=wsum[0];
            #pragma unroll
            for(int i=1;i<8;++i) m=fmaxf(m,wsum[i]);
            misc[0]=m*(1.0f/127.0f);
            misc[1]=(m>0.f)?(127.0f/m):0.f;
        }
        if(w==1){
            float m=Se1[lane];
            #pragma unroll
            for(int i=1;i<8;++i) m=fmaxf(m,Se1[lane+i*32]);
            #pragma unroll
            for(int o=16;o>0;o>>=1) m=fmaxf(m,__shfl_xor_sync(0xFFFFFFFFu,m,o));
            if(lane==0) misc[2]=m;
        }
    }
    __syncthreads();
    const float see=misc[0], inv_see=misc[1], Se1max=misc[2];
    // quantize emb -> eq[c4][k]
    {
        int k=tid;
        #pragma unroll 8
        for(int c4=0;c4<32;++c4){
            const float* ep=E+k*132+c4*4;
            int q0=__float2int_rn(ep[0]*inv_see);
            int q1=__float2int_rn(ep[1]*inv_see);
            int q2=__float2int_rn(ep[2]*inv_see);
            int q3=__float2int_rn(ep[3]*inv_see);
            eq[c4*256+k]=(q0&255)|((q1&255)<<8)|((q2&255)<<16)|(q3<<24);
        }
    }
    __syncthreads();

    const int n0=(tid>>5)*8;        // warp owns 8 queries
    const int k0=lane*8;            // lane owns 8 codes
    float lsum=0.f;

    for(int tile=blockIdx.x; tile<N_TILES; tile+=GRID){
        const int b=tile>>6, hw0=(tile&63)<<6;
        const float* zb=z+(size_t)b*(C_DIM*HW)+hw0;

        // ---- stage z fp32 ----
        #pragma unroll
        for(int i=0;i<8;++i){
            int idx=tid+i*NTH;            // 2048 float4
            int c=idx>>4, n4=(idx&15)<<2;
            *(float4*)(zf+c*68+n4)=*(const float4*)(zb+(size_t)c*HW+n4);
        }
        __syncthreads();

        // ---- per-query reductions: A, sum|z|, max|z| ----
        {
            int n=tid&63, part=tid>>6;
            const float* zp=zf+(part*32)*68+n;
            float a=0.f,s1=0.f,mx=0.f;
            #pragma unroll 8
            for(int j=0;j<32;++j){
                float v=zp[j*68];
                a=__fmaf_rn(v,v,a); s1+=fabsf(v); mx=fmaxf(mx,fabsf(v));
            }
            RA[part*64+n]=a; RS[part*64+n]=s1; RM[part*64+n]=mx;
        }
        __syncthreads();
        if(tid<64){
            int n=tid;
            An[n]=((RA[n]+RA[64+n])+RA[128+n])+RA[192+n];
            float s1=RS[n]+RS[64+n]+RS[128+n]+RS[192+n];
            Sz1[n]=s1;
            float mx=fmaxf(fmaxf(RM[n],RM[64+n]),fmaxf(RM[128+n],RM[192+n]));
            float szn=mx*(1.0f/127.0f);
            qin[n]=(mx>0.f)?(127.0f/mx):0.f;
            alp[n]=-2.0f*szn*see;
            win[n]=szn*Se1max+see*(s1+64.0f*szn)+1.5e-4f;
            cnt[n]=0;
        }
        __syncthreads();

        // ---- quantize z -> zq[c4][n] ----
        {
            int c4=tid>>3, nb=(tid&7)*8;
            const float* zp=zf+(c4*4)*68;
            #pragma unroll
            for(int jj=0;jj<8;++jj){
                int n=nb+jj;
                float iv=qin[n];
                int q0=__float2int_rn(zp[n]*iv);
                int q1=__float2int_rn(zp[68+n]*iv);
                int q2=__float2int_rn(zp[136+n]*iv);
                int q3=__float2int_rn(zp[204+n]*iv);
                zq[c4*64+n]=(q0&255)|((q1&255)<<8)|((q2&255)<<16)|(q3<<24);
            }
        }
        __syncthreads();

        // ---- int8 GEMM: 32 dp4a steps ----
        int acc[8][8];
        #pragma unroll
        for(int i=0;i<8;++i)
            #pragma unroll
            for(int j=0;j<8;++j) acc[i][j]=0;
        #pragma unroll 4
        for(int c4=0;c4<32;++c4){
            int4 za0=*(const int4*)(zq+c4*64+n0);
            int4 za1=*(const int4*)(zq+c4*64+n0+4);
            int4 eb0=*(const int4*)(eq+c4*256+k0);
            int4 eb1=*(const int4*)(eq+c4*256+k0+4);
            int zr[8]={za0.x,za0.y,za0.z,za0.w,za1.x,za1.y,za1.z,za1.w};
            int er[8]={eb0.x,eb0.y,eb0.z,eb0.w,eb1.x,eb1.y,eb1.z,eb1.w};
            #pragma unroll
            for(int i=0;i<8;++i)
                #pragma unroll
                for(int j=0;j<8;++j) acc[i][j]=__dp4a(zr[i],er[j],acc[i][j]);
        }

        // ---- approx scores (int->float exact), warp-local min + window ----
        float se8[8], sf[8][8];
        {
            float2 s0=*(const float2*)(se+k0),   s1=*(const float2*)(se+k0+2);
            float2 s2=*(const float2*)(se+k0+4), s3=*(const float2*)(se+k0+6);
            se8[0]=s0.x; se8[1]=s0.y; se8[2]=s1.x; se8[3]=s1.y;
            se8[4]=s2.x; se8[5]=s2.y; se8[6]=s3.x; se8[7]=s3.y;
        }
        float thr8[8];
        #pragma unroll
        for(int i=0;i<8;++i){
            float A=An[n0+i], na=alp[n0+i];
            float m=1e30f;
            #pragma unroll
            for(int j=0;j<8;++j){
                float s=__fmaf_rn(na,(float)acc[i][j],A)+se8[j];
                sf[i][j]=s; m=fminf(m,s);
            }
            #pragma unroll
            for(int o=16;o>0;o>>=1) m=fminf(m,__shfl_xor_sync(0xFFFFFFFFu,m,o));
            thr8[i]=m+win[n0+i];
        }
        // ---- candidate collection ----
        #pragma unroll
        for(int i=0;i<8;++i){
            float t=thr8[i];
            #pragma unroll
            for(int j=0;j<8;++j){
                if(sf[i][j]<=t){
                    int slot=atomicAdd(&cnt[n0+i],1);
                    if(slot<CAP) cand[(n0+i)*CAP+slot]=k0+j;
                }
            }
        }
        __syncthreads();

        // ---- exact rescore (bit-exact reference semantics) ----
        if(tid<64){
            int q=tid, m=cnt[q], kbest;
            float A=An[q];
            if(m==1){ kbest=cand[q*CAP]; }
            else{
                unsigned long long best=~0ull;
                if(m<=CAP){
                    for(int i=0;i<m;++i){
                        int k=cand[q*CAP+i];
                        float g=0.f;
                        const float* ek=E+k*132;
                        #pragma unroll 8
                        for(int c=0;c<C_DIM;++c) g=__fmaf_rn(zf[c*68+q],ek[c],g);
                        float d=__fadd_rn(__fadd_rn(A,-__fmul_rn(2.0f,g)),se[k]);
                        unsigned long long key=((unsigned long long)fkey(d)<<32)|(unsigned)k;
                        if(key<best) best=key;
                    }
                }else{
                    for(int k=0;k<256;++k){
                        float g=0.f;
                        const float* ek=E+k*132;
                        #pragma unroll 8
                        for(int c=0;c<C_DIM;++c) g=__fmaf_rn(zf[c*68+q],ek[c],g);
                        float d=__fadd_rn(__fadd_rn(A,-__fmul_rn(2.0f,g)),se[k]);
                        unsigned long long key=((unsigned long long)fkey(d)<<32)|(unsigned)k;
                        if(key<best) best=key;
                    }
                }
                kbest=(int)(best&255u);
            }
            idx_s[q]=kbest;
        }
        __syncthreads();

        // ---- epilogue: q_ste = RN(z + RN(q-z)); loss += RN(q-z)^2 ----
        {
            float* outb=out_q+(size_t)b*(C_DIM*HW)+hw0;
            #pragma unroll
            for(int i=0;i<8;++i){
                int idx=tid+i*NTH;
                int c=idx>>4, n4=(idx&15)<<2;
                float4 zv=*(const float4*)(zf+c*68+n4);
                int ka=idx_s[n4],kb=idx_s[n4+1],kc=idx_s[n4+2],kd=idx_s[n4+3];
                float q0=E[ka*132+c],q1=E[kb*132+c],q2=E[kc*132+c],q3=E[kd*132+c];
                float d0=q0-zv.x,d1=q1-zv.y,d2=q2-zv.z,d3=q3-zv.w;
                lsum=__fmaf_rn(d0,d0,lsum); lsum=__fmaf_rn(d1,d1,lsum);
                lsum=__fmaf_rn(d2,d2,lsum); lsum=__fmaf_rn(d3,d3,lsum);
                float4 o=make_float4(zv.x+d0,zv.y+d1,zv.z+d2,zv.w+d3);
                *(float4*)(outb+(size_t)c*HW+n4)=o;
            }
            if(out_idx!=nullptr && tid<64)
                out_idx[(size_t)tile*BN+tid]=(float)idx_s[tid];
        }
        __syncthreads();
    }

    // ---- per-CTA loss slot (no atomics, no zero kernel) ----
    #pragma unroll
    for(int o=16;o>0;o>>=1) lsum+=__shfl_xor_sync(0xFFFFFFFFu,lsum,o);
    if(lane==0) wsum[w]=lsum;
    __syncthreads();
    if(tid==0){
        float t=0.f;
        #pragma unroll
        for(int i=0;i<8;++i) t+=wsum[i];
        d_loss_arr[blockIdx.x]=(double)t;
    }
}

__global__ void vq_finalize(float* out_s){
    double s=0.0;
    for(int i=0;i<GRID;++i) s+=d_loss_arr[i];
    double mse=s*(1.0/(double)NQ);
    out_s[0]=(float)(0.25*mse);
    out_s[1]=(float)mse;
}

extern "C" void kernel_launch(void* const* d_in, const int* in_sizes, int n_in,
                              void* d_out, int out_size){
    const float *z,*emb;
    if(n_in>=2 && in_sizes[0]==256*C_DIM){ emb=(const float*)d_in[0]; z=(const float*)d_in[1]; }
    else { z=(const float*)d_in[0]; emb=(const float*)d_in[1]; }
    float* out=(float*)d_out;
    cudaFuncSetAttribute(vq_main, cudaFuncAttributeMaxDynamicSharedMemorySize, SMEM_BYTES);
    float* out_idx=nullptr; float* out_s=nullptr;
    long long osz=(long long)out_size;
    if(osz>=(long long)NQ+N_TOT) out_idx=out+NQ;
    if(osz>=(long long)NQ+N_TOT+2) out_s=out+NQ+N_TOT;
    vq_main<<<GRID,NTH,SMEM_BYTES>>>(z,emb,out,out_idx);
    if(out_s) vq_finalize<<<1,1>>>(out_s);
}